// round 10
// baseline (speedup 1.0000x reference)
#include <cuda_runtime.h>

// BuiltSWAP on qubits A=0, B=7 of a 13-qubit state, batch 64.
// Reference computes state @ M (M = SWAP permutation matrix); after the
// bit-index flip in _swap_matrix this is out[b, j] = state[b, swap_bits(j)]
// with bits 12 and 5 exchanged (SWAP is an involution). The harness output
// buffer is n float32 (complex64 reference coerced to float32 = real part),
// so only state_re is permuted; state_im and M (256 MB) are dead inputs.
//
// The swap mask 0x1020 touches only the low 13 bits, so it applies directly
// to the flat float index g = b*8192 + j (batch bits unaffected):
//   src_global(g) = g ^ (bit12(g) != bit5(g) ? 0x1020 : 0)
//
// TERMINAL SHAPE. Measured ncu kernel dur across shapes: 512x256/f4
// 4.10-4.61us, 256x256/f2x2 4.38us, 1024x256/f2 4.42us (occ 72%), 128x256/
// f4x4 4.70us -- all within noise. The kernel sits at the launch/ramp
// overhead floor (~3us fixed + ~1.5us L2-resident traffic); occupancy tripled
// with zero dur change, refuting further shape tuning. Pin the shape with the
// best observed wall time (4.67us) and minimal SASS: 512 CTAs x 256 threads,
// exactly one float4 load+store per thread, no bounds checks (exact cover).

#define BIT_HI 12
#define BIT_LO 5
#define SWAP_MASK ((1u << BIT_HI) | (1u << BIT_LO))  // 0x1020

#define THREADS 256
#define BLOCKS 512   // 512*256 threads * 4 floats = 524288 floats. Exact.

__device__ __forceinline__ unsigned swap_src_flat(unsigned g) {
    // g is a flat float index; exchange bits 12 and 5 (within the state row).
    unsigned diff = ((g >> BIT_HI) ^ (g >> BIT_LO)) & 1u;
    return g ^ (diff ? SWAP_MASK : 0u);
}

__global__ void __launch_bounds__(THREADS)
swap_gate_real_kernel(const float* __restrict__ state_re,
                      float* __restrict__ out)
{
    const unsigned t = blockIdx.x * THREADS + threadIdx.x;  // float4 index
    const unsigned e = t * 4u;                              // flat float index
    const float4 v = *reinterpret_cast<const float4*>(state_re + swap_src_flat(e));
    *reinterpret_cast<float4*>(out + e) = v;
}

extern "C" void kernel_launch(void* const* d_in, const int* in_sizes, int n_in,
                              void* d_out, int out_size)
{
    const float* state_re = (const float*)d_in[0];
    // d_in[1] = state_im, d_in[2] = M: dead inputs (output is real part only).
    float* out = (float*)d_out;
    swap_gate_real_kernel<<<BLOCKS, THREADS>>>(state_re, out);
}

// round 13
// speedup vs baseline: 1.4795x; 1.4795x over previous
#include <cuda_runtime.h>

// BuiltSWAP on qubits A=0, B=7 of a 13-qubit state, batch 64.
// Reference computes state @ M (M = SWAP permutation matrix); after the
// bit-index flip in _swap_matrix this is out[b, j] = state[b, swap_bits(j)]
// with bits 12 and 5 exchanged (SWAP is an involution). The harness output
// buffer is n float32 (complex64 reference coerced to float32 = real part),
// so only state_re is permuted; state_im and M (256 MB) are dead inputs.
//
// Branchless flat-index swap: the mask 0x1020 touches only low-13 bits, so
// with d = ((g >> 7) ^ g) & 0x20  (bit-5 slot set iff bit12 != bit5):
//   src(g) = g ^ d ^ (d << 7)
// -- 3 fixed-latency ALU ops, no predicate/select chain.
//
// TERMINAL SHAPE. ncu kernel dur across all tested shapes (occ 12%..72%,
// MLP 1..4, f2/f4): 4.10-4.70us, statistically flat -> the kernel sits at the
// launch/ramp overhead floor (~3us fixed + ~1.5us L2-resident traffic). Wall
// variance (4.67-6.91us for identical source) is harness noise. Pin: 512
// CTAs x 256 threads, one float4 load+store per thread, exact cover.

#define THREADS 256
#define BLOCKS 512   // 512*256 threads * 4 floats = 524288 floats. Exact.

__device__ __forceinline__ unsigned swap_src_flat(unsigned g) {
    // Exchange bits 12 and 5 of g, branchlessly.
    unsigned d = ((g >> 7) ^ g) & 0x20u;   // bit5 set iff bit12 != bit5
    return g ^ d ^ (d << 7);               // flips both bits when they differ
}

__global__ void __launch_bounds__(THREADS)
swap_gate_real_kernel(const float* __restrict__ state_re,
                      float* __restrict__ out)
{
    const unsigned t = blockIdx.x * THREADS + threadIdx.x;  // float4 index
    const unsigned e = t * 4u;                              // flat float index
    const float4 v = *reinterpret_cast<const float4*>(state_re + swap_src_flat(e));
    *reinterpret_cast<float4*>(out + e) = v;
}

extern "C" void kernel_launch(void* const* d_in, const int* in_sizes, int n_in,
                              void* d_out, int out_size)
{
    const float* state_re = (const float*)d_in[0];
    // d_in[1] = state_im, d_in[2] = M: dead inputs (output is real part only).
    float* out = (float*)d_out;
    swap_gate_real_kernel<<<BLOCKS, THREADS>>>(state_re, out);
}